// round 8
// baseline (speedup 1.0000x reference)
#include <cuda_runtime.h>

#define NB    128     // batch
#define CIN   512
#define HW    64      // 8*8 pixels per batch
#define OUTC  256
#define EMB   4096
#define DD    4096
#define NPIX  8192    // NB*HW
#define ES    32      // subclasses per class
#define NC    128     // classes
#define DSPLIT 16     // d-splits in loss kernel (256 d each)
#define CSPLIT 4      // c-splits in enc kernel (128 c each)

// ---- scratch (no allocs allowed) ----
__device__ float g_M2[EMB * CIN];                 // -2 * (cc @ W)
__device__ float g_vc[EMB];                       // ||cc_j||^2 - 2*cc_j.bias
__device__ int   g_flags[NC];
__device__ float g_epart[NB * CSPLIT * ES * HW];  // 4 MB enc partial dots
__device__ int   g_slot[NPIX];                    // pixel -> slot (within batch)
__device__ int   g_slotrow[NB * ES];              // (b, slot) -> teacher row e
__device__ int   g_nslot[NB];                     // distinct rows per batch
__device__ float g_lpart[NB * DSPLIT * HW * 4];   // loss partials (r,dot,t0,t1)
__device__ float g_partial[NB];

typedef unsigned long long ull;

__device__ __forceinline__ ull fma2(ull a, ull b, ull c) {
    ull d;
    asm("fma.rn.f32x2 %0, %1, %2, %3;" : "=l"(d) : "l"(a), "l"(b), "l"(c));
    return d;
}
__device__ __forceinline__ ull pack2(float x, float y) {
    ull p;
    asm("mov.b64 %0, {%1, %2};" : "=l"(p) : "f"(x), "f"(y));
    return p;
}
__device__ __forceinline__ void unpack2(ull p, float& x, float& y) {
    asm("mov.b64 {%0, %1}, %2;" : "=f"(x), "=f"(y) : "l"(p));
}

// ---------------- K1b: vc[j] = ||cc_j||^2 - 2*cc_j.bias (+ flags in block 0)
__global__ void k_vc(const float* __restrict__ cc, const float* __restrict__ bias,
                     const int* __restrict__ labels) {
    if (blockIdx.x == 0) {          // whole block enters: __syncthreads is safe
        int t = threadIdx.x;
        if (t < NC) g_flags[t] = 0;
        __syncthreads();
        if (t < NB) g_flags[labels[t]] = 1;
    }
    int warp = threadIdx.x >> 5, lane = threadIdx.x & 31;
    int j = blockIdx.x * 8 + warp;
    const float* row = cc + j * OUTC;
    float cn = 0.f, bb = 0.f;
#pragma unroll
    for (int o = lane; o < OUTC; o += 32) {
        float v = row[o];
        cn += v * v;
        bb += v * bias[o];
    }
#pragma unroll
    for (int s = 16; s; s >>= 1) {
        cn += __shfl_xor_sync(~0u, cn, s);
        bb += __shfl_xor_sync(~0u, bb, s);
    }
    if (lane == 0) g_vc[j] = cn - 2.f * bb;
}

// ---------------- K1: M2 = -2 * cc @ W   (64x64 tile, conflict-free LDS) ----
// grid (CIN/64, EMB/64) = (8, 64), 256 threads.
__global__ void __launch_bounds__(256) k_M2(const float* __restrict__ cc,
                                            const float* __restrict__ W) {
    int c0 = blockIdx.x * 64;
    int j0 = blockIdx.y * 64;
    int cls = j0 >> 5;
    if (!g_flags[cls] && !g_flags[cls + 1]) return;   // class absent -> never read

    __shared__ float As[64][68];   // [j_local][o_local]
    __shared__ float Bs[64][68];   // [o_local][c_local]

    int t = threadIdx.x;
    int tx = t & 15;       // cols: {tx*2, tx*2+1} and {32+tx*2, 32+tx*2+1}
    int ty = t >> 4;       // j group of 4

    ull acc[4][2];
#pragma unroll
    for (int jj = 0; jj < 4; jj++) { acc[jj][0] = pack2(0.f, 0.f); acc[jj][1] = pack2(0.f, 0.f); }

    for (int kt = 0; kt < 4; kt++) {
        int o0 = kt * 64;
#pragma unroll
        for (int k = 0; k < 4; k++) {
            int f = t + k * 256;
            int row = f >> 4, q = f & 15;
            *(float4*)&As[row][q * 4] = *(const float4*)(cc + (j0 + row) * OUTC + o0 + q * 4);
            *(float4*)&Bs[row][q * 4] = *(const float4*)(W + (o0 + row) * CIN + c0 + q * 4);
        }
        __syncthreads();
#pragma unroll
        for (int o = 0; o < 64; o++) {
            // lanes (tx 0..15) read tx*8B: one contiguous 128B window -> conflict-free
            ull b0 = *(ull*)&Bs[o][tx * 2];
            ull b1 = *(ull*)&Bs[o][32 + tx * 2];
#pragma unroll
            for (int jj = 0; jj < 4; jj++) {
                float a = As[ty * 4 + jj][o];
                ull aa = pack2(a, a);
                acc[jj][0] = fma2(aa, b0, acc[jj][0]);
                acc[jj][1] = fma2(aa, b1, acc[jj][1]);
            }
        }
        __syncthreads();
    }
#pragma unroll
    for (int jj = 0; jj < 4; jj++) {
        int j = j0 + ty * 4 + jj;
        float x, y;
        unpack2(acc[jj][0], x, y);
        g_M2[j * CIN + c0 + tx * 2]      = -2.f * x;
        g_M2[j * CIN + c0 + tx * 2 + 1]  = -2.f * y;
        unpack2(acc[jj][1], x, y);
        g_M2[j * CIN + c0 + 32 + tx * 2]     = -2.f * x;
        g_M2[j * CIN + c0 + 32 + tx * 2 + 1] = -2.f * y;
    }
}

// ---------------- K2a: enc partial dots, split over c (CSPLIT=4) ----------
// grid (CSPLIT, NB), 256 threads. Partial over c in [cs*128, cs*128+128).
// Inner product vectorized over c-parity with fma.rn.f32x2 (even/odd sums,
// horizontal add at the end): halves FFMA instruction count.
__global__ void __launch_bounds__(256) k_enc_part(const float* __restrict__ F,
                                                  const int* __restrict__ labels) {
    int cs = blockIdx.x;
    int b  = blockIdx.y;
    int l  = labels[b];
    int jbase = l * ES;
    int c0 = cs * 128;

    __shared__ float Fs[128][68];   // [c_local][p]  pitch 68: 16B-aligned rows
    __shared__ float Ms[32][132];   // [j_local][c_local]

    int t = threadIdx.x;
    int p = t & 63, jg = t >> 6;

    const float* Fb = F + (size_t)b * CIN * HW;

#pragma unroll
    for (int k = 0; k < 8; k++) {
        int f = t + k * 256; int row = f >> 4, q = f & 15;
        *(float4*)&Fs[row][q * 4] = *(const float4*)(Fb + (c0 + row) * HW + q * 4);
    }
#pragma unroll
    for (int k = 0; k < 4; k++) {
        int f = t + k * 256; int row = f >> 5, q = f & 31;
        *(float4*)&Ms[row][q * 4] = *(const float4*)(g_M2 + (size_t)(jbase + row) * CIN + c0 + q * 4);
    }
    __syncthreads();

    ull accp[8];
#pragma unroll
    for (int jj = 0; jj < 8; jj++) accp[jj] = pack2(0.f, 0.f);

#pragma unroll 4
    for (int c = 0; c < 128; c += 4) {
        ull aa01 = pack2(Fs[c][p],     Fs[c + 1][p]);
        ull aa23 = pack2(Fs[c + 2][p], Fs[c + 3][p]);
#pragma unroll
        for (int jj = 0; jj < 8; jj++) {
            const ull* mp = (const ull*)&Ms[jg * 8 + jj][c];   // 16B-aligned (c%4==0, pitch 132)
            accp[jj] = fma2(aa01, mp[0], accp[jj]);
            accp[jj] = fma2(aa23, mp[1], accp[jj]);
        }
    }

#pragma unroll
    for (int jj = 0; jj < 8; jj++) {
        int j = jg * 8 + jj;
        float lo, hi;
        unpack2(accp[jj], lo, hi);
        g_epart[(((size_t)b * CSPLIT + cs) * ES + j) * HW + p] = lo + hi;
    }
}

// ---------------- K2b: combine + argmin + slot dedupe (256 threads) -------
__global__ void __launch_bounds__(256) k_enc_comb(const int* __restrict__ labels) {
    int b = blockIdx.x;
    int t = threadIdx.x;
    int p = t & 63, jg = t >> 6;     // jg handles j in [jg*8, jg*8+8)
    int jbase = labels[b] * ES;

    float bestv = 3.4e38f;
    int bestj = jg * 8;
#pragma unroll
    for (int jj = 0; jj < 8; jj++) {
        int j = jg * 8 + jj;
        float v = g_vc[jbase + j];
#pragma unroll
        for (int cs = 0; cs < CSPLIT; cs++)
            v += g_epart[(((size_t)b * CSPLIT + cs) * ES + j) * HW + p];
        if (v < bestv) { bestv = v; bestj = j; }   // ascending j: first occurrence
    }

    __shared__ float bv[4][HW];
    __shared__ int   bj[4][HW];
    __shared__ int   mark[ES];
    __shared__ int   slotid[ES];
    __shared__ int   bfin[HW];
    bv[jg][p] = bestv;
    bj[jg][p] = bestj;
    if (t < ES) mark[t] = 0;
    __syncthreads();
    if (t < HW) {
        float vb = bv[0][t]; int jb = bj[0][t];
#pragma unroll
        for (int g = 1; g < 4; g++)          // ascending groups + strict < : first occurrence
            if (bv[g][t] < vb) { vb = bv[g][t]; jb = bj[g][t]; }
        bfin[t] = jb;
        mark[jb] = 1;                        // racing 1-writes: benign
    }
    __syncthreads();
    if (t < 32) {                            // warp 0 (uniform)
        unsigned m = __ballot_sync(~0u, mark[t] != 0);
        slotid[t] = __popc(m & ((1u << t) - 1u));
        if (t == 0) g_nslot[b] = __popc(m);
        if (mark[t]) g_slotrow[b * ES + slotid[t]] = jbase + t;
    }
    __syncthreads();
    if (t < HW) g_slot[b * HW + t] = slotid[bfin[t]];
}

// ---------------- K3: loss partials with deduped teacher staging ----------
// grid (DSPLIT, NB), 256 threads. Block covers 256 d (4 chunks of 64).
__global__ void __launch_bounds__(256) k_loss_part(const float* __restrict__ scores,
                                                   const float* __restrict__ ts) {
    int ds = blockIdx.x;
    int b  = blockIdx.y;
    int t  = threadIdx.x;

    __shared__ float Tsm[32][68];        // distinct teacher rows only
    __shared__ float st0[32], st1[32];   // per-slot sum t, sum t*log t (this d-range)
    __shared__ int   sslot[HW];
    __shared__ float red[4][HW][2];      // r, dot

    int sg = t >> 3, sq = t & 7;         // staging: 32 groups x 8 threads
    int cp_p = t & 63, cp_dg = t >> 6;   // compute: pixel x d-subgroup(16 d)

    int nd = g_nslot[b];
    if (t < HW) sslot[t] = g_slot[b * HW + t];
    int erow = (sg < nd) ? g_slotrow[b * ES + sg] : 0;
    const float* trow = ts + (size_t)erow * DD + ds * 256;
    const float* sbase = scores + (size_t)b * DD * HW + (size_t)(ds * 256) * HW + cp_p;

    float r = 0.f, dot = 0.f, a0 = 0.f, a1 = 0.f;
    __syncthreads();                     // sslot visible

    for (int ch = 0; ch < 4; ch++) {
        if (sg < nd) {
#pragma unroll
            for (int k = 0; k < 2; k++) {
                int off = (sq + 8 * k) * 4;
                float4 v = *(const float4*)(trow + ch * 64 + off);
                *(float4*)&Tsm[sg][off] = v;
                a0 += v.x + v.y + v.z + v.w;
                a1 += (v.x > 0.f ? v.x * __logf(v.x) : 0.f);
                a1 += (v.y > 0.f ? v.y * __logf(v.y) : 0.f);
                a1 += (v.z > 0.f ? v.z * __logf(v.z) : 0.f);
                a1 += (v.w > 0.f ? v.w * __logf(v.w) : 0.f);
            }
        }
        __syncthreads();

        int sl = sslot[cp_p];
        const float* sp = sbase + (size_t)(ch * 64 + cp_dg * 16) * HW;
#pragma unroll
        for (int u = 0; u < 4; u++) {
            float4 tv = *(float4*)&Tsm[sl][cp_dg * 16 + u * 4];
            float s0 = sp[0], s1 = sp[HW], s2 = sp[2 * HW], s3 = sp[3 * HW];
            sp += 4 * HW;
            // scores ~ N(0,1): single-pass exp is safe in fp32
            r += __expf(s0) + __expf(s1) + __expf(s2) + __expf(s3);
            dot += tv.x * s0 + tv.y * s1 + tv.z * s2 + tv.w * s3;
        }
        __syncthreads();
    }

    // per-slot t0/t1: reduce within each 8-thread staging group
#pragma unroll
    for (int s = 4; s; s >>= 1) {
        a0 += __shfl_xor_sync(~0u, a0, s);
        a1 += __shfl_xor_sync(~0u, a1, s);
    }
    if (sq == 0 && sg < nd) { st0[sg] = a0; st1[sg] = a1; }

    red[cp_dg][cp_p][0] = r;
    red[cp_dg][cp_p][1] = dot;
    __syncthreads();
    if (t < HW) {
        float4 o;
        o.x = red[0][t][0] + red[1][t][0] + red[2][t][0] + red[3][t][0];
        o.y = red[0][t][1] + red[1][t][1] + red[2][t][1] + red[3][t][1];
        int sl = sslot[t];
        o.z = st0[sl];
        o.w = st1[sl];
        *(float4*)&g_lpart[(((size_t)b * DSPLIT + ds) * HW + t) * 4] = o;
    }
}

// ---------------- K4: per-pixel loss + per-batch reduce ----------------
__global__ void k_loss_comb() {
    int b = blockIdx.x;
    int p = threadIdx.x;            // 64 threads
    float R = 0.f, D = 0.f, T0 = 0.f, T1 = 0.f;
#pragma unroll
    for (int ds = 0; ds < DSPLIT; ds++) {
        float4 v = *(float4*)&g_lpart[(((size_t)b * DSPLIT + ds) * HW + p) * 4];
        R += v.x; D += v.y; T0 += v.z; T1 += v.w;
    }
    float lse = __logf(R);
    float lp = T1 - D + T0 * lse;

    __shared__ float sm[HW];
    sm[p] = lp;
    __syncthreads();
    if (p == 0) {
        float s = 0.f;
        for (int i = 0; i < HW; i++) s += sm[i];
        g_partial[b] = s;
    }
}

// ---------------- K5: final deterministic reduction ----------------
__global__ void k_final(float* __restrict__ out) {
    __shared__ float sm[NB];
    int t = threadIdx.x;
    sm[t] = g_partial[t];
    __syncthreads();
    if (t == 0) {
        float s = 0.f;
        for (int i = 0; i < NB; i++) s += sm[i];
        out[0] = s / (float)NPIX;
    }
}

extern "C" void kernel_launch(void* const* d_in, const int* in_sizes, int n_in,
                              void* d_out, int out_size) {
    const float* feat   = (const float*)d_in[0];   // [128,512,8,8]
    const float* scores = (const float*)d_in[1];   // [128,4096,8,8]
    const int*   labels = (const int*)  d_in[2];   // [128]
    const float* W      = (const float*)d_in[3];   // [256,512]
    const float* bias   = (const float*)d_in[4];   // [256]
    const float* cc     = (const float*)d_in[5];   // [4096,256]
    const float* ts     = (const float*)d_in[6];   // [4096,4096]
    float* out = (float*)d_out;

    k_vc<<<EMB / 8, 256>>>(cc, bias, labels);      // + class flags (block 0)
    k_M2<<<dim3(CIN / 64, EMB / 64), 256>>>(cc, W);
    k_enc_part<<<dim3(CSPLIT, NB), 256>>>(feat, labels);
    k_enc_comb<<<NB, 256>>>(labels);
    k_loss_part<<<dim3(DSPLIT, NB), 256>>>(scores, ts);
    k_loss_comb<<<NB, 64>>>();
    k_final<<<1, 128>>>(out);
}

// round 9
// speedup vs baseline: 1.0569x; 1.0569x over previous
#include <cuda_runtime.h>

#define NB    128     // batch
#define CIN   512
#define HW    64      // 8*8 pixels per batch
#define OUTC  256
#define EMB   4096
#define DD    4096
#define NPIX  8192    // NB*HW
#define ES    32      // subclasses per class
#define NC    128     // classes
#define DSPLIT 32     // d-splits in loss kernel (128 d each)
#define CSPLIT 4      // c-splits in enc kernel (128 c each)

// ---- scratch (no allocs allowed) ----
__device__ float g_M2[EMB * CIN];                 // -2 * (cc @ W)
__device__ float g_vc[EMB];                       // ||cc_j||^2 - 2*cc_j.bias
__device__ int   g_flags[NC];
__device__ float g_epart[NB * CSPLIT * ES * HW];  // 4 MB enc partial dots
__device__ int   g_slot[NPIX];                    // pixel -> slot (within batch)
__device__ int   g_slotrow[NB * ES];              // (b, slot) -> teacher row e
__device__ int   g_nslot[NB];                     // distinct rows per batch
__device__ float g_lpart[NB * DSPLIT * HW * 4];   // 4 MB loss partials (r,dot,t0,t1)
__device__ float g_partial[NB];

typedef unsigned long long ull;

__device__ __forceinline__ ull fma2(ull a, ull b, ull c) {
    ull d;
    asm("fma.rn.f32x2 %0, %1, %2, %3;" : "=l"(d) : "l"(a), "l"(b), "l"(c));
    return d;
}
__device__ __forceinline__ ull pack2(float x, float y) {
    ull p;
    asm("mov.b64 %0, {%1, %2};" : "=l"(p) : "f"(x), "f"(y));
    return p;
}
__device__ __forceinline__ void unpack2(ull p, float& x, float& y) {
    asm("mov.b64 {%0, %1}, %2;" : "=f"(x), "=f"(y) : "l"(p));
}

// ---------------- K1b: vc[j] = ||cc_j||^2 - 2*cc_j.bias (+ flags in block 0)
__global__ void k_vc(const float* __restrict__ cc, const float* __restrict__ bias,
                     const int* __restrict__ labels) {
    if (blockIdx.x == 0) {          // whole block enters: __syncthreads is safe
        int t = threadIdx.x;
        if (t < NC) g_flags[t] = 0;
        __syncthreads();
        if (t < NB) g_flags[labels[t]] = 1;
    }
    int warp = threadIdx.x >> 5, lane = threadIdx.x & 31;
    int j = blockIdx.x * 8 + warp;
    const float* row = cc + j * OUTC;
    float cn = 0.f, bb = 0.f;
#pragma unroll
    for (int o = lane; o < OUTC; o += 32) {
        float v = row[o];
        cn += v * v;
        bb += v * bias[o];
    }
#pragma unroll
    for (int s = 16; s; s >>= 1) {
        cn += __shfl_xor_sync(~0u, cn, s);
        bb += __shfl_xor_sync(~0u, bb, s);
    }
    if (lane == 0) g_vc[j] = cn - 2.f * bb;
}

// ---------------- K1: M2 = -2 * cc @ W   (64x64 tile, conflict-free LDS) ----
// grid (CIN/64, EMB/64) = (8, 64), 256 threads.
__global__ void __launch_bounds__(256) k_M2(const float* __restrict__ cc,
                                            const float* __restrict__ W) {
    int c0 = blockIdx.x * 64;
    int j0 = blockIdx.y * 64;
    int cls = j0 >> 5;
    if (!g_flags[cls] && !g_flags[cls + 1]) return;   // class absent -> never read

    __shared__ float As[64][68];   // [j_local][o_local]
    __shared__ float Bs[64][68];   // [o_local][c_local]

    int t = threadIdx.x;
    int tx = t & 15;       // cols: {tx*2, tx*2+1} and {32+tx*2, 32+tx*2+1}
    int ty = t >> 4;       // j group of 4

    ull acc[4][2];
#pragma unroll
    for (int jj = 0; jj < 4; jj++) { acc[jj][0] = pack2(0.f, 0.f); acc[jj][1] = pack2(0.f, 0.f); }

    for (int kt = 0; kt < 4; kt++) {
        int o0 = kt * 64;
#pragma unroll
        for (int k = 0; k < 4; k++) {
            int f = t + k * 256;
            int row = f >> 4, q = f & 15;
            *(float4*)&As[row][q * 4] = *(const float4*)(cc + (j0 + row) * OUTC + o0 + q * 4);
            *(float4*)&Bs[row][q * 4] = *(const float4*)(W + (o0 + row) * CIN + c0 + q * 4);
        }
        __syncthreads();
#pragma unroll
        for (int o = 0; o < 64; o++) {
            // lanes (tx 0..15) read tx*8B: one contiguous 128B window -> conflict-free
            ull b0 = *(ull*)&Bs[o][tx * 2];
            ull b1 = *(ull*)&Bs[o][32 + tx * 2];
#pragma unroll
            for (int jj = 0; jj < 4; jj++) {
                float a = As[ty * 4 + jj][o];
                ull aa = pack2(a, a);
                acc[jj][0] = fma2(aa, b0, acc[jj][0]);
                acc[jj][1] = fma2(aa, b1, acc[jj][1]);
            }
        }
        __syncthreads();
    }
#pragma unroll
    for (int jj = 0; jj < 4; jj++) {
        int j = j0 + ty * 4 + jj;
        float x, y;
        unpack2(acc[jj][0], x, y);
        g_M2[j * CIN + c0 + tx * 2]      = -2.f * x;
        g_M2[j * CIN + c0 + tx * 2 + 1]  = -2.f * y;
        unpack2(acc[jj][1], x, y);
        g_M2[j * CIN + c0 + 32 + tx * 2]     = -2.f * x;
        g_M2[j * CIN + c0 + 32 + tx * 2 + 1] = -2.f * y;
    }
}

// ---------------- K2a: enc partial dots, split over c (CSPLIT=4) ----------
__global__ void __launch_bounds__(256) k_enc_part(const float* __restrict__ F,
                                                  const int* __restrict__ labels) {
    int cs = blockIdx.x;
    int b  = blockIdx.y;
    int l  = labels[b];
    int jbase = l * ES;
    int c0 = cs * 128;

    __shared__ float Fs[128][68];   // [c_local][p]  pitch 68: 16B-aligned rows
    __shared__ float Ms[32][132];   // [j_local][c_local]

    int t = threadIdx.x;
    int p = t & 63, jg = t >> 6;

    const float* Fb = F + (size_t)b * CIN * HW;

#pragma unroll
    for (int k = 0; k < 8; k++) {
        int f = t + k * 256; int row = f >> 4, q = f & 15;
        *(float4*)&Fs[row][q * 4] = *(const float4*)(Fb + (c0 + row) * HW + q * 4);
    }
#pragma unroll
    for (int k = 0; k < 4; k++) {
        int f = t + k * 256; int row = f >> 5, q = f & 31;
        *(float4*)&Ms[row][q * 4] = *(const float4*)(g_M2 + (size_t)(jbase + row) * CIN + c0 + q * 4);
    }
    __syncthreads();

    ull accp[8];
#pragma unroll
    for (int jj = 0; jj < 8; jj++) accp[jj] = pack2(0.f, 0.f);

#pragma unroll 4
    for (int c = 0; c < 128; c += 4) {
        ull aa01 = pack2(Fs[c][p],     Fs[c + 1][p]);
        ull aa23 = pack2(Fs[c + 2][p], Fs[c + 3][p]);
#pragma unroll
        for (int jj = 0; jj < 8; jj++) {
            const ull* mp = (const ull*)&Ms[jg * 8 + jj][c];
            accp[jj] = fma2(aa01, mp[0], accp[jj]);
            accp[jj] = fma2(aa23, mp[1], accp[jj]);
        }
    }

#pragma unroll
    for (int jj = 0; jj < 8; jj++) {
        int j = jg * 8 + jj;
        float lo, hi;
        unpack2(accp[jj], lo, hi);
        g_epart[(((size_t)b * CSPLIT + cs) * ES + j) * HW + p] = lo + hi;
    }
}

// ---------------- K2b: combine + argmin + slot dedupe (256 threads) -------
__global__ void __launch_bounds__(256) k_enc_comb(const int* __restrict__ labels) {
    int b = blockIdx.x;
    int t = threadIdx.x;
    int p = t & 63, jg = t >> 6;     // jg handles j in [jg*8, jg*8+8)
    int jbase = labels[b] * ES;

    float bestv = 3.4e38f;
    int bestj = jg * 8;
#pragma unroll
    for (int jj = 0; jj < 8; jj++) {
        int j = jg * 8 + jj;
        float v = g_vc[jbase + j];
#pragma unroll
        for (int cs = 0; cs < CSPLIT; cs++)
            v += g_epart[(((size_t)b * CSPLIT + cs) * ES + j) * HW + p];
        if (v < bestv) { bestv = v; bestj = j; }   // ascending j: first occurrence
    }

    __shared__ float bv[4][HW];
    __shared__ int   bj[4][HW];
    __shared__ int   mark[ES];
    __shared__ int   slotid[ES];
    __shared__ int   bfin[HW];
    bv[jg][p] = bestv;
    bj[jg][p] = bestj;
    if (t < ES) mark[t] = 0;
    __syncthreads();
    if (t < HW) {
        float vb = bv[0][t]; int jb = bj[0][t];
#pragma unroll
        for (int g = 1; g < 4; g++)          // ascending groups + strict < : first occurrence
            if (bv[g][t] < vb) { vb = bv[g][t]; jb = bj[g][t]; }
        bfin[t] = jb;
        mark[jb] = 1;                        // racing 1-writes: benign
    }
    __syncthreads();
    if (t < 32) {                            // warp 0 (uniform)
        unsigned m = __ballot_sync(~0u, mark[t] != 0);
        slotid[t] = __popc(m & ((1u << t) - 1u));
        if (t == 0) g_nslot[b] = __popc(m);
        if (mark[t]) g_slotrow[b * ES + slotid[t]] = jbase + t;
    }
    __syncthreads();
    if (t < HW) g_slot[b * HW + t] = slotid[bfin[t]];
}

// ---------------- K3: loss partials, single-stage teacher + LDG.128 -------
// grid (DSPLIT, NB), 256 threads. Block covers 128 d.
// Thread (pq, dgrp): pixels [pq*4, pq*4+4), d in [dgrp*8, dgrp*8+8).
__global__ void __launch_bounds__(256) k_loss_part(const float* __restrict__ scores,
                                                   const float* __restrict__ ts) {
    int ds = blockIdx.x;
    int b  = blockIdx.y;
    int t  = threadIdx.x;

    __shared__ float Tsm[32][132];       // distinct teacher rows, this 128-d slice
    __shared__ float st0[32], st1[32];   // per-slot sum t, sum t*log t (this slice)
    __shared__ int   sslot[HW];
    __shared__ float redr[16][16][4];    // [dgrp][pq][i]
    __shared__ float redd[16][16][4];

    int sg = t >> 3, sq = t & 7;         // staging: 32 teams x 8 threads
    int pq = t & 15, dgrp = t >> 4;      // compute mapping

    int nd = g_nslot[b];
    if (t < HW) sslot[t] = g_slot[b * HW + t];
    int erow = (sg < nd) ? g_slotrow[b * ES + sg] : 0;
    const float* trow = ts + (size_t)erow * DD + ds * 128;

    // stage this block's full 128-d teacher slice once; fold per-slot t0/t1
    float a0 = 0.f, a1 = 0.f;
    if (sg < nd) {
#pragma unroll
        for (int k = 0; k < 4; k++) {
            int off = (sq + 8 * k) * 4;
            float4 v = *(const float4*)(trow + off);
            *(float4*)&Tsm[sg][off] = v;
            a0 += v.x + v.y + v.z + v.w;
            a1 += (v.x > 0.f ? v.x * __logf(v.x) : 0.f);
            a1 += (v.y > 0.f ? v.y * __logf(v.y) : 0.f);
            a1 += (v.z > 0.f ? v.z * __logf(v.z) : 0.f);
            a1 += (v.w > 0.f ? v.w * __logf(v.w) : 0.f);
        }
    }
    // per-slot reduce within each 8-thread team (before the single barrier)
#pragma unroll
    for (int s = 4; s; s >>= 1) {
        a0 += __shfl_xor_sync(~0u, a0, s);
        a1 += __shfl_xor_sync(~0u, a1, s);
    }
    if (sq == 0 && sg < nd) { st0[sg] = a0; st1[sg] = a1; }
    __syncthreads();                     // Tsm, st0/st1, sslot all visible

    int sl0 = sslot[pq * 4], sl1 = sslot[pq * 4 + 1];
    int sl2 = sslot[pq * 4 + 2], sl3 = sslot[pq * 4 + 3];
    const float* sp = scores + (size_t)b * DD * HW
                    + (size_t)(ds * 128 + dgrp * 8) * HW + pq * 4;

    float r0 = 0.f, r1 = 0.f, r2 = 0.f, r3 = 0.f;
    float d0 = 0.f, d1 = 0.f, d2 = 0.f, d3 = 0.f;
#pragma unroll
    for (int u = 0; u < 8; u++) {
        float4 s = *(const float4*)(sp + (size_t)u * HW);   // 4 pixels, one d
        int d = dgrp * 8 + u;
        r0 += __expf(s.x); d0 += Tsm[sl0][d] * s.x;
        r1 += __expf(s.y); d1 += Tsm[sl1][d] * s.y;
        r2 += __expf(s.z); d2 += Tsm[sl2][d] * s.z;
        r3 += __expf(s.w); d3 += Tsm[sl3][d] * s.w;
    }

    redr[dgrp][pq][0] = r0; redr[dgrp][pq][1] = r1;
    redr[dgrp][pq][2] = r2; redr[dgrp][pq][3] = r3;
    redd[dgrp][pq][0] = d0; redd[dgrp][pq][1] = d1;
    redd[dgrp][pq][2] = d2; redd[dgrp][pq][3] = d3;
    __syncthreads();

    if (t < HW) {
        int pq2 = t >> 2, i = t & 3;
        float R = 0.f, D = 0.f;
#pragma unroll
        for (int g = 0; g < 16; g++) { R += redr[g][pq2][i]; D += redd[g][pq2][i]; }
        int sl = sslot[t];
        float4 o;
        o.x = R; o.y = D; o.z = st0[sl]; o.w = st1[sl];
        *(float4*)&g_lpart[(((size_t)b * DSPLIT + ds) * HW + t) * 4] = o;
    }
}

// ---------------- K4: per-pixel loss + per-batch reduce ----------------
__global__ void k_loss_comb() {
    int b = blockIdx.x;
    int p = threadIdx.x;            // 64 threads
    float R = 0.f, D = 0.f, T0 = 0.f, T1 = 0.f;
#pragma unroll 8
    for (int ds = 0; ds < DSPLIT; ds++) {
        float4 v = *(float4*)&g_lpart[(((size_t)b * DSPLIT + ds) * HW + p) * 4];
        R += v.x; D += v.y; T0 += v.z; T1 += v.w;
    }
    float lse = __logf(R);
    float lp = T1 - D + T0 * lse;

    __shared__ float sm[HW];
    sm[p] = lp;
    __syncthreads();
    if (p == 0) {
        float s = 0.f;
        for (int i = 0; i < HW; i++) s += sm[i];
        g_partial[b] = s;
    }
}

// ---------------- K5: final deterministic reduction ----------------
__global__ void k_final(float* __restrict__ out) {
    __shared__ float sm[NB];
    int t = threadIdx.x;
    sm[t] = g_partial[t];
    __syncthreads();
    if (t == 0) {
        float s = 0.f;
        for (int i = 0; i < NB; i++) s += sm[i];
        out[0] = s / (float)NPIX;
    }
}

extern "C" void kernel_launch(void* const* d_in, const int* in_sizes, int n_in,
                              void* d_out, int out_size) {
    const float* feat   = (const float*)d_in[0];   // [128,512,8,8]
    const float* scores = (const float*)d_in[1];   // [128,4096,8,8]
    const int*   labels = (const int*)  d_in[2];   // [128]
    const float* W      = (const float*)d_in[3];   // [256,512]
    const float* bias   = (const float*)d_in[4];   // [256]
    const float* cc     = (const float*)d_in[5];   // [4096,256]
    const float* ts     = (const float*)d_in[6];   // [4096,4096]
    float* out = (float*)d_out;

    k_vc<<<EMB / 8, 256>>>(cc, bias, labels);      // + class flags (block 0)
    k_M2<<<dim3(CIN / 64, EMB / 64), 256>>>(cc, W);
    k_enc_part<<<dim3(CSPLIT, NB), 256>>>(feat, labels);
    k_enc_comb<<<NB, 256>>>(labels);
    k_loss_part<<<dim3(DSPLIT, NB), 256>>>(scores, ts);
    k_loss_comb<<<NB, 64>>>();
    k_final<<<1, 128>>>(out);
}

// round 11
// speedup vs baseline: 1.0860x; 1.0276x over previous
#include <cuda_runtime.h>

#define NB    128     // batch
#define CIN   512
#define HW    64      // 8*8 pixels per batch
#define OUTC  256
#define EMB   4096
#define DD    4096
#define NPIX  8192    // NB*HW
#define ES    32      // subclasses per class
#define DSPLIT 32     // d-splits in loss kernel (128 d each)

// ---- scratch (no allocs allowed) ----
__device__ float g_M2[EMB * CIN];                 // -2 * (cc @ W)
__device__ float g_vc[EMB];                       // ||cc_j||^2 - 2*cc_j.bias
__device__ int   g_slot[NPIX];                    // pixel -> slot (within batch)
__device__ int   g_slotrow[NB * ES];              // (b, slot) -> teacher row e
__device__ int   g_nslot[NB];                     // distinct rows per batch
__device__ float g_lpart[NB * DSPLIT * HW * 4];   // 4 MB loss partials (r,dot,t0,t1)

typedef unsigned long long ull;

__device__ __forceinline__ ull fma2(ull a, ull b, ull c) {
    ull d;
    asm("fma.rn.f32x2 %0, %1, %2, %3;" : "=l"(d) : "l"(a), "l"(b), "l"(c));
    return d;
}
__device__ __forceinline__ ull pack2(float x, float y) {
    ull p;
    asm("mov.b64 %0, {%1, %2};" : "=l"(p) : "f"(x), "f"(y));
    return p;
}
__device__ __forceinline__ void unpack2(ull p, float& x, float& y) {
    asm("mov.b64 {%0, %1}, %2;" : "=f"(x), "=f"(y) : "l"(p));
}

// ---------------- K1: M2 = -2*cc@W (64x64 tile) + vc + class-skip + out-zero
// grid (CIN/64, EMB/64) = (8, 64), 256 threads.
__global__ void __launch_bounds__(256) k_M2v(const float* __restrict__ cc,
                                             const float* __restrict__ W,
                                             const float* __restrict__ bias,
                                             const int* __restrict__ labels,
                                             float* __restrict__ out) {
    // smem arrays carrying float4/ull accesses MUST be 16B-aligned explicitly:
    // bare __shared__ float arrays get only 4B alignment (R10 trap).
    __shared__ __align__(16) float As[64][68];   // [j_local][o_local]
    __shared__ __align__(16) float Bs[64][68];   // [o_local][c_local]
    __shared__ int spresent;

    int t = threadIdx.x;
    int c0 = blockIdx.x * 64;
    int j0 = blockIdx.y * 64;
    int cls0 = j0 >> 5;

    if (t == 0) spresent = 0;
    __syncthreads();
    if (t < NB) {
        int lb = labels[t];
        if (lb == cls0 || lb == cls0 + 1) spresent = 1;   // racing 1-writes: benign
    }
    if (blockIdx.x == 0 && blockIdx.y == 0 && t == 0) out[0] = 0.f;  // for atomic final
    __syncthreads();
    if (!spresent) return;                  // class absent -> rows never read

    // vc for this j-range (c-chunk-0 blocks only): 8 warps x 8 j
    if (blockIdx.x == 0) {
        int warp = t >> 5, lane = t & 31;
#pragma unroll
        for (int jj = 0; jj < 8; jj++) {
            int j = j0 + warp * 8 + jj;
            const float* row = cc + j * OUTC;
            float cn = 0.f, bb = 0.f;
#pragma unroll
            for (int o = lane; o < OUTC; o += 32) {
                float v = row[o];
                cn += v * v;
                bb += v * bias[o];
            }
#pragma unroll
            for (int s = 16; s; s >>= 1) {
                cn += __shfl_xor_sync(~0u, cn, s);
                bb += __shfl_xor_sync(~0u, bb, s);
            }
            if (lane == 0) g_vc[j] = cn - 2.f * bb;
        }
    }

    int tx = t & 15;       // cols: {tx*2, tx*2+1} and {32+tx*2, 32+tx*2+1}
    int ty = t >> 4;       // j group of 4

    ull acc[4][2];
#pragma unroll
    for (int jj = 0; jj < 4; jj++) { acc[jj][0] = pack2(0.f, 0.f); acc[jj][1] = pack2(0.f, 0.f); }

    for (int kt = 0; kt < 4; kt++) {
        int o0 = kt * 64;
#pragma unroll
        for (int k = 0; k < 4; k++) {
            int f = t + k * 256;
            int row = f >> 4, q = f & 15;
            *(float4*)&As[row][q * 4] = *(const float4*)(cc + (j0 + row) * OUTC + o0 + q * 4);
            *(float4*)&Bs[row][q * 4] = *(const float4*)(W + (o0 + row) * CIN + c0 + q * 4);
        }
        __syncthreads();
#pragma unroll
        for (int o = 0; o < 64; o++) {
            // lanes (tx 0..15) read tx*8B: contiguous 128B window -> conflict-free
            ull b0 = *(ull*)&Bs[o][tx * 2];
            ull b1 = *(ull*)&Bs[o][32 + tx * 2];
#pragma unroll
            for (int jj = 0; jj < 4; jj++) {
                float a = As[ty * 4 + jj][o];
                ull aa = pack2(a, a);
                acc[jj][0] = fma2(aa, b0, acc[jj][0]);
                acc[jj][1] = fma2(aa, b1, acc[jj][1]);
            }
        }
        __syncthreads();
    }
#pragma unroll
    for (int jj = 0; jj < 4; jj++) {
        int j = j0 + ty * 4 + jj;
        float x, y;
        unpack2(acc[jj][0], x, y);
        g_M2[j * CIN + c0 + tx * 2]      = -2.f * x;
        g_M2[j * CIN + c0 + tx * 2 + 1]  = -2.f * y;
        unpack2(acc[jj][1], x, y);
        g_M2[j * CIN + c0 + 32 + tx * 2]     = -2.f * x;
        g_M2[j * CIN + c0 + 32 + tx * 2 + 1] = -2.f * y;
    }
}

// ---------------- K2: fused enc: full-K dots + argmin + slot dedupe -------
// grid NB, 256 threads. acc carried across 4 c-chunks of 128.
__global__ void __launch_bounds__(256) k_enc(const float* __restrict__ F,
                                             const int* __restrict__ labels) {
    __shared__ __align__(16) float Fs[128][68];   // [c_local][p]  16B-aligned rows
    __shared__ __align__(16) float Ms[32][132];   // [j_local][c_local]

    int b = blockIdx.x, t = threadIdx.x;
    int p = t & 63, jg = t >> 6;
    int jbase = labels[b] * ES;

    const float* Fb = F + (size_t)b * CIN * HW;

    ull accp[8];
#pragma unroll
    for (int jj = 0; jj < 8; jj++) accp[jj] = pack2(0.f, 0.f);

    for (int cs = 0; cs < 4; cs++) {
        int c0 = cs * 128;
#pragma unroll
        for (int k = 0; k < 8; k++) {
            int f = t + k * 256; int row = f >> 4, q = f & 15;
            *(float4*)&Fs[row][q * 4] = *(const float4*)(Fb + (c0 + row) * HW + q * 4);
        }
#pragma unroll
        for (int k = 0; k < 4; k++) {
            int f = t + k * 256; int row = f >> 5, q = f & 31;
            *(float4*)&Ms[row][q * 4] = *(const float4*)(g_M2 + (size_t)(jbase + row) * CIN + c0 + q * 4);
        }
        __syncthreads();

#pragma unroll 4
        for (int c = 0; c < 128; c += 4) {
            ull aa01 = pack2(Fs[c][p],     Fs[c + 1][p]);
            ull aa23 = pack2(Fs[c + 2][p], Fs[c + 3][p]);
#pragma unroll
            for (int jj = 0; jj < 8; jj++) {
                const ull* mp = (const ull*)&Ms[jg * 8 + jj][c];
                accp[jj] = fma2(aa01, mp[0], accp[jj]);
                accp[jj] = fma2(aa23, mp[1], accp[jj]);
            }
        }
        __syncthreads();
    }

    float bestv = 3.4e38f;
    int bestj = jg * 8;
#pragma unroll
    for (int jj = 0; jj < 8; jj++) {
        int j = jg * 8 + jj;
        float lo, hi;
        unpack2(accp[jj], lo, hi);
        float v = (lo + hi) + g_vc[jbase + j];
        if (v < bestv) { bestv = v; bestj = j; }   // ascending j: first occurrence
    }

    // reuse Ms for combine scratch (all staged data consumed; scalar accesses only)
    float* bv   = (float*)Ms;              // [4*64]
    int*   bj   = (int*)Ms + 256;          // [4*64]
    int*   bfin = (int*)Ms + 512;          // [64]
    int*   mark = (int*)Ms + 576;          // [32]
    int*   slid = (int*)Ms + 608;          // [32]

    bv[jg * 64 + p] = bestv;
    bj[jg * 64 + p] = bestj;
    if (t < ES) mark[t] = 0;
    __syncthreads();
    if (t < HW) {
        float vb = bv[t]; int jb = bj[t];
#pragma unroll
        for (int g = 1; g < 4; g++)        // ascending groups + strict < : first occurrence
            if (bv[g * 64 + t] < vb) { vb = bv[g * 64 + t]; jb = bj[g * 64 + t]; }
        bfin[t] = jb;
        mark[jb] = 1;                      // racing 1-writes: benign
    }
    __syncthreads();
    if (t < 32) {                          // warp 0 (uniform)
        unsigned m = __ballot_sync(~0u, mark[t] != 0);
        slid[t] = __popc(m & ((1u << t) - 1u));
        if (t == 0) g_nslot[b] = __popc(m);
        if (mark[t]) g_slotrow[b * ES + slid[t]] = jbase + t;
    }
    __syncthreads();
    if (t < HW) g_slot[b * HW + t] = slid[bfin[t]];
}

// ---------------- K3: loss partials, single-stage teacher + LDG.128 -------
// grid (DSPLIT, NB), 256 threads. Block covers 128 d.
__global__ void __launch_bounds__(256) k_loss_part(const float* __restrict__ scores,
                                                   const float* __restrict__ ts) {
    __shared__ __align__(16) float Tsm[32][132]; // distinct teacher rows, 128-d slice
    __shared__ __align__(16) float redr[16][16][4];
    __shared__ __align__(16) float redd[16][16][4];
    __shared__ float st0[32], st1[32];
    __shared__ int   sslot[HW];

    int ds = blockIdx.x;
    int b  = blockIdx.y;
    int t  = threadIdx.x;

    int sg = t >> 3, sq = t & 7;         // staging: 32 teams x 8 threads
    int pq = t & 15, dgrp = t >> 4;      // compute mapping

    int nd = g_nslot[b];
    if (t < HW) sslot[t] = g_slot[b * HW + t];
    int erow = (sg < nd) ? g_slotrow[b * ES + sg] : 0;
    const float* trow = ts + (size_t)erow * DD + ds * 128;

    // stage the block's full 128-d teacher slice once; fold per-slot t0/t1
    float a0 = 0.f, a1 = 0.f;
    if (sg < nd) {
#pragma unroll
        for (int k = 0; k < 4; k++) {
            int off = (sq + 8 * k) * 4;
            float4 v = *(const float4*)(trow + off);
            *(float4*)&Tsm[sg][off] = v;
            a0 += v.x + v.y + v.z + v.w;
            a1 += (v.x > 0.f ? v.x * __logf(v.x) : 0.f);
            a1 += (v.y > 0.f ? v.y * __logf(v.y) : 0.f);
            a1 += (v.z > 0.f ? v.z * __logf(v.z) : 0.f);
            a1 += (v.w > 0.f ? v.w * __logf(v.w) : 0.f);
        }
    }
#pragma unroll
    for (int s = 4; s; s >>= 1) {
        a0 += __shfl_xor_sync(~0u, a0, s);
        a1 += __shfl_xor_sync(~0u, a1, s);
    }
    if (sq == 0 && sg < nd) { st0[sg] = a0; st1[sg] = a1; }
    __syncthreads();                     // Tsm, st0/st1, sslot all visible

    int sl0 = sslot[pq * 4], sl1 = sslot[pq * 4 + 1];
    int sl2 = sslot[pq * 4 + 2], sl3 = sslot[pq * 4 + 3];
    const float* sp = scores + (size_t)b * DD * HW
                    + (size_t)(ds * 128 + dgrp * 8) * HW + pq * 4;

    float r0 = 0.f, r1 = 0.f, r2 = 0.f, r3 = 0.f;
    float d0 = 0.f, d1 = 0.f, d2 = 0.f, d3 = 0.f;
#pragma unroll
    for (int u = 0; u < 8; u++) {
        float4 s = *(const float4*)(sp + (size_t)u * HW);   // 4 pixels, one d
        int d = dgrp * 8 + u;
        r0 += __expf(s.x); d0 += Tsm[sl0][d] * s.x;
        r1 += __expf(s.y); d1 += Tsm[sl1][d] * s.y;
        r2 += __expf(s.z); d2 += Tsm[sl2][d] * s.z;
        r3 += __expf(s.w); d3 += Tsm[sl3][d] * s.w;
    }

    redr[dgrp][pq][0] = r0; redr[dgrp][pq][1] = r1;
    redr[dgrp][pq][2] = r2; redr[dgrp][pq][3] = r3;
    redd[dgrp][pq][0] = d0; redd[dgrp][pq][1] = d1;
    redd[dgrp][pq][2] = d2; redd[dgrp][pq][3] = d3;
    __syncthreads();

    if (t < HW) {
        int pq2 = t >> 2, i = t & 3;
        float R = 0.f, D = 0.f;
#pragma unroll
        for (int g = 0; g < 16; g++) { R += redr[g][pq2][i]; D += redd[g][pq2][i]; }
        int sl = sslot[t];
        float4 o;
        o.x = R; o.y = D; o.z = st0[sl]; o.w = st1[sl];
        *(float4*)&g_lpart[(((size_t)b * DSPLIT + ds) * HW + t) * 4] = o;
    }
}

// ---------------- K4: per-pixel loss + per-batch reduce + atomic final ----
// grid NB, 256 threads. Thread (p, g): sums ds in [g*8, g*8+8).
__global__ void __launch_bounds__(256) k_loss_comb(float* __restrict__ out) {
    __shared__ __align__(16) float red[4][HW][4];
    __shared__ float ls[HW];

    int b = blockIdx.x, t = threadIdx.x;
    int p = t & 63, g = t >> 6;

    float R = 0.f, D = 0.f, T0 = 0.f, T1 = 0.f;
#pragma unroll
    for (int k = 0; k < 8; k++) {
        int ds = g * 8 + k;
        float4 v = *(float4*)&g_lpart[(((size_t)b * DSPLIT + ds) * HW + p) * 4];
        R += v.x; D += v.y; T0 += v.z; T1 += v.w;   // t0/t1 are per-d-slice partials
    }

    red[g][p][0] = R; red[g][p][1] = D; red[g][p][2] = T0; red[g][p][3] = T1;
    __syncthreads();
    if (t < HW) {
        float Rf = 0.f, Df = 0.f, T0f = 0.f, T1f = 0.f;
#pragma unroll
        for (int q = 0; q < 4; q++) {
            Rf += red[q][t][0]; Df += red[q][t][1];
            T0f += red[q][t][2]; T1f += red[q][t][3];
        }
        float lse = __logf(Rf);
        ls[t] = T1f - Df + T0f * lse;
    }
    __syncthreads();
    if (t == 0) {
        float s = 0.f;
        for (int i = 0; i < HW; i++) s += ls[i];
        atomicAdd(out, s / (float)NPIX);
    }
}

extern "C" void kernel_launch(void* const* d_in, const int* in_sizes, int n_in,
                              void* d_out, int out_size) {
    const float* feat   = (const float*)d_in[0];   // [128,512,8,8]
    const float* scores = (const float*)d_in[1];   // [128,4096,8,8]
    const int*   labels = (const int*)  d_in[2];   // [128]
    const float* W      = (const float*)d_in[3];   // [256,512]
    const float* bias   = (const float*)d_in[4];   // [256]
    const float* cc     = (const float*)d_in[5];   // [4096,256]
    const float* ts     = (const float*)d_in[6];   // [4096,4096]
    float* out = (float*)d_out;

    k_M2v<<<dim3(CIN / 64, EMB / 64), 256>>>(cc, W, bias, labels, out);
    k_enc<<<NB, 256>>>(feat, labels);
    k_loss_part<<<dim3(DSPLIT, NB), 256>>>(scores, ts);
    k_loss_comb<<<NB, 256>>>(out);
}